// round 17
// baseline (speedup 1.0000x reference)
#include <cuda_runtime.h>

// ARXCell, B = 16384 rows:
//   a2[b]       = dot(iw, itdl[b,0:2048]) + dot(ow, otdl[b,0:64]) + bias
//   itdl_new[b] = [ itdl[b,64:2048], input[b,0:64] ]
//   otdl_new[b] = [ otdl[b,1:64], a2[b] ]
//   outputs[b]  = a2[b]
//
// Output layout: [ outputs(16384) | itdl_new(16384*2048) | otdl_new(16384*64) ]
//
// FOUR ROWS PER WARP, fully unrolled (no loop back-edge): 512 CTAs at occ-4
// fit in ONE wave (592 capacity) -> zero wave transitions, no tail imbalance.
// One iw load feeds 4 rows (quarter weight traffic). The 4 per-iteration
// stream loads are independent -> natural MLP=4 per warp (same proven L1tex
// queue pressure as the PF=4 single-row design) without prefetch registers.
// itdl still read ONCE per element (feeds dot AND shifted store).

#define BATCH       16384
#define DI          2048
#define DO          64
#define NIN         64
#define DI4         (DI / 4)     // 512 float4 per row
#define SHIFT4      (NIN / 4)    // 16 float4 shift
#define RPW         4            // rows per warp

__global__ __launch_bounds__(256, 4)
void arx_cell_kernel(const float* __restrict__ input,   // [B, 64]
                     const float* __restrict__ itdl,    // [B, 2048]
                     const float* __restrict__ otdl,    // [B, 64]
                     const float* __restrict__ iw,      // [2048]
                     const float* __restrict__ ow,      // [64]
                     const float* __restrict__ bias,    // [1]
                     float* __restrict__ out_a2,        // [B]
                     float* __restrict__ out_itdl,      // [B, 2048]
                     float* __restrict__ out_otdl)      // [B, 64]
{
    const int gtid = blockIdx.x * blockDim.x + threadIdx.x;
    const int wrp  = gtid >> 5;
    const int lane = gtid & 31;
    const int r0   = wrp * RPW;          // rows r0 .. r0+3
    if (r0 >= BATCH) return;

    const float4* __restrict__ iw4 = reinterpret_cast<const float4*>(iw);
    const float4* __restrict__ it0 = reinterpret_cast<const float4*>(itdl) + (size_t)r0 * DI4;
    float4* __restrict__ nt0 = reinterpret_cast<float4*>(out_itdl) + (size_t)r0 * DI4;

    float acc0 = 0.f, acc1 = 0.f, acc2 = 0.f, acc3 = 0.f;

    #pragma unroll
    for (int j = 0; j < 16; ++j) {
        const int v = j * 32 + lane;
        // 4 independent stream loads -> MLP=4 per warp.
        const float4 c0 = __ldcs(it0 + 0 * DI4 + v);
        const float4 c1 = __ldcs(it0 + 1 * DI4 + v);
        const float4 c2 = __ldcs(it0 + 2 * DI4 + v);
        const float4 c3 = __ldcs(it0 + 3 * DI4 + v);
        const float4 w  = iw4[v];            // ONE weight load feeds 4 rows

        acc0 = fmaf(c0.x, w.x, acc0); acc0 = fmaf(c0.y, w.y, acc0);
        acc0 = fmaf(c0.z, w.z, acc0); acc0 = fmaf(c0.w, w.w, acc0);
        acc1 = fmaf(c1.x, w.x, acc1); acc1 = fmaf(c1.y, w.y, acc1);
        acc1 = fmaf(c1.z, w.z, acc1); acc1 = fmaf(c1.w, w.w, acc1);
        acc2 = fmaf(c2.x, w.x, acc2); acc2 = fmaf(c2.y, w.y, acc2);
        acc2 = fmaf(c2.z, w.z, acc2); acc2 = fmaf(c2.w, w.w, acc2);
        acc3 = fmaf(c3.x, w.x, acc3); acc3 = fmaf(c3.y, w.y, acc3);
        acc3 = fmaf(c3.z, w.z, acc3); acc3 = fmaf(c3.w, w.w, acc3);

        if (v >= SHIFT4) {
            __stcs(nt0 + 0 * DI4 + (v - SHIFT4), c0);
            __stcs(nt0 + 1 * DI4 + (v - SHIFT4), c1);
            __stcs(nt0 + 2 * DI4 + (v - SHIFT4), c2);
            __stcs(nt0 + 3 * DI4 + (v - SHIFT4), c3);
        }
    }

    // Small streams (after the main loop to keep register pressure low).
    const float2* __restrict__ in2 = reinterpret_cast<const float2*>(input) + (size_t)r0 * (NIN / 2);
    const float2* __restrict__ ot2 = reinterpret_cast<const float2*>(otdl)  + (size_t)r0 * (DO  / 2);
    const float2 w2 = reinterpret_cast<const float2*>(ow)[lane];
    const float  bb = bias[0];

    float2* __restrict__ no2 = reinterpret_cast<float2*>(out_otdl + (size_t)r0 * DO);

    #pragma unroll
    for (int r = 0; r < RPW; ++r) {
        // Append input at itdl_new[r0+r, 1984:2048].
        const float2 iv = __ldcs(in2 + r * (NIN / 2) + lane);
        __stcs(reinterpret_cast<float2*>(out_itdl + (size_t)(r0 + r) * DI + (DI - NIN)) + lane, iv);

        // otdl dot contribution + reduction + shift store for row r.
        const float2 ov = __ldcs(ot2 + r * (DO / 2) + lane);
        float acc = (r == 0) ? acc0 : (r == 1) ? acc1 : (r == 2) ? acc2 : acc3;
        acc = fmaf(ov.x, w2.x, acc);
        acc = fmaf(ov.y, w2.y, acc);

        #pragma unroll
        for (int off = 16; off > 0; off >>= 1)
            acc += __shfl_xor_sync(0xffffffffu, acc, off);
        const float a2 = acc + bb;

        // otdl shift-by-1, coalesced float2 per lane; slot 63 = a2.
        const float nxt = __shfl_down_sync(0xffffffffu, ov.x, 1);
        float2 o2;
        o2.x = ov.y;
        o2.y = (lane == 31) ? a2 : nxt;
        __stcs(no2 + r * (DO / 2) + lane, o2);

        if (lane == 0)
            out_a2[r0 + r] = a2;
    }
}

extern "C" void kernel_launch(void* const* d_in, const int* in_sizes, int n_in,
                              void* d_out, int out_size) {
    const float* input = (const float*)d_in[0];
    const float* itdl  = (const float*)d_in[1];
    const float* otdl  = (const float*)d_in[2];
    const float* iw    = (const float*)d_in[3];
    const float* ow    = (const float*)d_in[4];
    const float* bias  = (const float*)d_in[5];

    float* out      = (float*)d_out;
    float* out_a2   = out;
    float* out_itdl = out + BATCH;
    float* out_otdl = out + BATCH + (size_t)BATCH * DI;

    const int threads = 256;                              // 8 warps -> 32 rows/CTA
    const int blocks  = BATCH / (RPW * (threads / 32));   // 512 -> single wave at occ-4

    arx_cell_kernel<<<blocks, threads>>>(input, itdl, otdl, iw, ow, bias,
                                         out_a2, out_itdl, out_otdl);
}